// round 1
// baseline (speedup 1.0000x reference)
#include <cuda_runtime.h>
#include <cuda_bf16.h>
#include <math.h>

// Problem constants
#define TOK   100352          // B * H * W = 32*56*56  (= 2048 windows * 49 tokens)
#define CCH   384
#define HID3  1152
#define HIDM  1536
#define NWIN  2048            // B * 64
#define NHEAD 12

// ---------------- scratch (device globals; no allocation allowed) ------------
__device__ float g_h  [(size_t)TOK * CCH];    // windowed LN output / attn out / LN2 out
__device__ float g_big[(size_t)TOK * HIDM];   // qkv (1152 cols used) / mlp hidden (1536)
__device__ float g_y  [(size_t)TOK * CCH];    // residual after attention

// map windowed row t -> flat (b*3136 + h*56 + w) index in the UNSHIFTED image
__device__ __forceinline__ int winrow_to_dst(int t) {
    int n  = t % 49;
    int w_ = t / 49;
    int b  = w_ >> 6;
    int nw = w_ & 63;
    int wh = nw >> 3, ww = nw & 7;
    int r = n / 7, c = n % 7;
    int h = wh * 7 + r + 3; if (h >= 56) h -= 56;   // window reverse + roll(+3)
    int w = ww * 7 + c + 3; if (w >= 56) w -= 56;
    return b * 3136 + h * 56 + w;
}

// ---------------- LayerNorm (+optional shift/window gather) ------------------
// windowed=1: block t is a windowed row; gather from rolled source pixel.
// windowed=0: identity layout.
__global__ void ln_kernel(const float* __restrict__ x, const float* __restrict__ g,
                          const float* __restrict__ b, float* __restrict__ out,
                          int windowed)
{
    int t = blockIdx.x;
    size_t src;
    if (windowed) {
        int n  = t % 49;
        int w_ = t / 49;
        int batch = w_ >> 6;
        int nw = w_ & 63;
        int wh = nw >> 3, ww = nw & 7;
        int r = n / 7, c = n % 7;
        int h  = wh * 7 + r + 3; if (h  >= 56) h  -= 56;   // roll(-3): src = (pos+3)%56
        int wc = ww * 7 + c + 3; if (wc >= 56) wc -= 56;
        src = ((size_t)batch * 3136 + h * 56 + wc) * CCH;
    } else {
        src = (size_t)t * CCH;
    }
    int tid = threadIdx.x;                 // 128 threads, 3 elems each
    float v0 = x[src + tid];
    float v1 = x[src + tid + 128];
    float v2 = x[src + tid + 256];
    float s  = v0 + v1 + v2;
    float ss = v0 * v0 + v1 * v1 + v2 * v2;
    #pragma unroll
    for (int o = 16; o; o >>= 1) {
        s  += __shfl_xor_sync(0xffffffffu, s,  o);
        ss += __shfl_xor_sync(0xffffffffu, ss, o);
    }
    __shared__ float sh_s[4], sh_q[4];
    int wid = tid >> 5, lane = tid & 31;
    if (lane == 0) { sh_s[wid] = s; sh_q[wid] = ss; }
    __syncthreads();
    float ts = sh_s[0] + sh_s[1] + sh_s[2] + sh_s[3];
    float tq = sh_q[0] + sh_q[1] + sh_q[2] + sh_q[3];
    float mean = ts * (1.0f / 384.0f);
    float var  = tq * (1.0f / 384.0f) - mean * mean;
    float inv  = rsqrtf(var + 1e-5f);
    size_t dst = (size_t)t * CCH;
    out[dst + tid]       = (v0 - mean) * inv * g[tid]       + b[tid];
    out[dst + tid + 128] = (v1 - mean) * inv * g[tid + 128] + b[tid + 128];
    out[dst + tid + 256] = (v2 - mean) * inv * g[tid + 256] + b[tid + 256];
}

// ---------------- GEMM: C[M,N] = A[M,K] @ B[K,N]  (+ fused epilogues) --------
// 128x64 block tile, BK=16, 256 threads, 8x4 per-thread microtile.
// MODE 0: C = acc + bias                               (QKV)
// MODE 1: y[dst] = resid[dst] + acc + bias  (window-reverse scatter)   (proj)
// MODE 2: C = gelu(acc + bias)                          (MLP fc1)
// MODE 3: C = resid + acc + bias                        (MLP fc2 + residual)
template<int MODE>
__global__ void __launch_bounds__(256)
gemm_kernel(const float* __restrict__ A, const float* __restrict__ B,
            float* __restrict__ C, const float* __restrict__ bias,
            const float* __restrict__ resid, int M, int N, int K)
{
    __shared__ float As[16][128];
    __shared__ float Bs[16][64];
    int tid = threadIdx.x;
    int tr = tid >> 4, tc = tid & 15;           // 16x16 thread grid
    int m0 = blockIdx.y * 128, n0 = blockIdx.x * 64;

    float acc[8][4];
    #pragma unroll
    for (int i = 0; i < 8; i++)
        #pragma unroll
        for (int j = 0; j < 4; j++) acc[i][j] = 0.0f;

    for (int k0 = 0; k0 < K; k0 += 16) {
        #pragma unroll
        for (int it = 0; it < 2; it++) {
            int slot = tid + it * 256;          // 512 float4 slots
            int row = slot >> 2, kc = (slot & 3) << 2;
            float4 v = *(const float4*)(A + (size_t)(m0 + row) * K + k0 + kc);
            As[kc + 0][row] = v.x; As[kc + 1][row] = v.y;
            As[kc + 2][row] = v.z; As[kc + 3][row] = v.w;
        }
        {
            int row = tid >> 4, c4 = (tid & 15) << 2;
            *(float4*)&Bs[row][c4] =
                *(const float4*)(B + (size_t)(k0 + row) * N + n0 + c4);
        }
        __syncthreads();
        #pragma unroll
        for (int k = 0; k < 16; k++) {
            float a[8], bfr[4];
            #pragma unroll
            for (int i = 0; i < 8; i++) a[i] = As[k][tr * 8 + i];
            #pragma unroll
            for (int j = 0; j < 4; j++) bfr[j] = Bs[k][tc * 4 + j];
            #pragma unroll
            for (int i = 0; i < 8; i++)
                #pragma unroll
                for (int j = 0; j < 4; j++) acc[i][j] += a[i] * bfr[j];
        }
        __syncthreads();
    }

    #pragma unroll
    for (int i = 0; i < 8; i++) {
        int row = m0 + tr * 8 + i;
        int dst = 0;
        if (MODE == 1) dst = winrow_to_dst(row);
        #pragma unroll
        for (int j = 0; j < 4; j++) {
            int col = n0 + tc * 4 + j;
            float v = acc[i][j] + bias[col];
            if (MODE == 0) {
                C[(size_t)row * N + col] = v;
            } else if (MODE == 1) {
                size_t o = (size_t)dst * CCH + col;
                C[o] = resid[o] + v;
            } else if (MODE == 2) {
                C[(size_t)row * N + col] = 0.5f * v * (1.0f + erff(v * 0.70710678118654752f));
            } else {
                size_t o = (size_t)row * CCH + col;
                C[o] = resid[o] + v;
            }
        }
    }
}

// ---------------- windowed attention: one block per (window, head) -----------
__global__ void __launch_bounds__(256)
attn_kernel(const float* __restrict__ qkv, const float* __restrict__ rpb,
            float* __restrict__ out)
{
    int blk  = blockIdx.x;          // 0 .. 24575
    int head = blk % NHEAD;
    int win  = blk / NHEAD;

    __shared__ float Qs[49][32], Ks[49][32], Vs[49][32];
    __shared__ float S[49][52];
    __shared__ int   regio[49];

    int tid = threadIdx.x;
    const float scale = 0.17677669529663687f;   // 32^-0.5
    size_t base = (size_t)win * 49 * HID3 + head * 32;

    for (int idx = tid; idx < 49 * 32; idx += 256) {
        int n = idx >> 5, d = idx & 31;
        size_t rb = base + (size_t)n * HID3 + d;
        Qs[n][d] = qkv[rb] * scale;
        Ks[n][d] = qkv[rb + 384];
        Vs[n][d] = qkv[rb + 768];
    }
    if (tid < 49) {
        int nw = win & 63;
        int wh = nw >> 3, ww = nw & 7;
        int r = tid / 7, c = tid % 7;
        int hh = wh * 7 + r, wg = ww * 7 + c;       // region in ORIGINAL img coords
        int rh = hh < 49 ? 0 : (hh < 53 ? 1 : 2);
        int rw = wg < 49 ? 0 : (wg < 53 ? 1 : 2);
        regio[tid] = rh * 3 + rw;
    }
    __syncthreads();

    // S = Q K^T + rel-pos-bias + shift mask
    for (int idx = tid; idx < 49 * 49; idx += 256) {
        int i = idx / 49, j = idx % 49;
        float s = 0.0f;
        #pragma unroll
        for (int d = 0; d < 32; d++) s += Qs[i][d] * Ks[j][d];
        int ri = i / 7, ci = i % 7, rj = j / 7, cj = j % 7;
        int rel = (ri - rj + 6) * 13 + (ci - cj + 6);
        s += rpb[rel * NHEAD + head];
        if (regio[i] != regio[j]) s -= 100.0f;
        S[i][j] = s;
    }
    __syncthreads();

    // row softmax: one warp per row
    int wid = tid >> 5, lane = tid & 31;
    for (int i = wid; i < 49; i += 8) {
        float v0 = S[i][lane];
        float v1 = (lane + 32 < 49) ? S[i][lane + 32] : -1e30f;
        float m = fmaxf(v0, v1);
        #pragma unroll
        for (int o = 16; o; o >>= 1) m = fmaxf(m, __shfl_xor_sync(0xffffffffu, m, o));
        float e0 = __expf(v0 - m);
        float e1 = (lane + 32 < 49) ? __expf(v1 - m) : 0.0f;
        float sum = e0 + e1;
        #pragma unroll
        for (int o = 16; o; o >>= 1) sum += __shfl_xor_sync(0xffffffffu, sum, o);
        float inv = 1.0f / sum;
        S[i][lane] = e0 * inv;
        if (lane + 32 < 49) S[i][lane + 32] = e1 * inv;
    }
    __syncthreads();

    // O = P V  -> out[win, n, head*32+d]  ([BnW, N, C] with head-major cols)
    for (int idx = tid; idx < 49 * 32; idx += 256) {
        int i = idx >> 5, d = idx & 31;
        float o = 0.0f;
        #pragma unroll
        for (int j = 0; j < 49; j++) o += S[i][j] * Vs[j][d];
        out[((size_t)win * 49 + i) * CCH + head * 32 + d] = o;
    }
}

// ---------------------------------- driver -----------------------------------
extern "C" void kernel_launch(void* const* d_in, const int* in_sizes, int n_in,
                              void* d_out, int out_size)
{
    const float* x      = (const float*)d_in[0];
    const float* g1     = (const float*)d_in[1];
    const float* b1     = (const float*)d_in[2];
    const float* w_qkv  = (const float*)d_in[3];
    const float* b_qkv  = (const float*)d_in[4];
    const float* w_proj = (const float*)d_in[5];
    const float* b_proj = (const float*)d_in[6];
    const float* rpb    = (const float*)d_in[7];
    const float* g2     = (const float*)d_in[8];
    const float* b2     = (const float*)d_in[9];
    const float* w1     = (const float*)d_in[10];
    const float* bm1    = (const float*)d_in[11];
    const float* w2     = (const float*)d_in[12];
    const float* bm2    = (const float*)d_in[13];
    float* out = (float*)d_out;

    float *h, *big, *y;
    cudaGetSymbolAddress((void**)&h,   g_h);
    cudaGetSymbolAddress((void**)&big, g_big);
    cudaGetSymbolAddress((void**)&y,   g_y);

    // 1) LN1 + roll(-3,-3) + window partition -> h [100352, 384]
    ln_kernel<<<TOK, 128>>>(x, g1, b1, h, 1);

    // 2) QKV: h @ w_qkv + b_qkv -> big [100352, 1152]
    gemm_kernel<0><<<dim3(HID3 / 64, TOK / 128), 256>>>(h, w_qkv, big, b_qkv, nullptr,
                                                        TOK, HID3, CCH);

    // 3) attention per (window, head) -> h [100352, 384]
    attn_kernel<<<NWIN * NHEAD, 256>>>(big, rpb, h);

    // 4) proj + window reverse + roll(+3,+3) + residual(x) -> y [100352, 384]
    gemm_kernel<1><<<dim3(CCH / 64, TOK / 128), 256>>>(h, w_proj, y, b_proj, x,
                                                       TOK, CCH, CCH);

    // 5) LN2 -> h
    ln_kernel<<<TOK, 128>>>(y, g2, b2, h, 0);

    // 6) fc1 + exact GELU -> big [100352, 1536]
    gemm_kernel<2><<<dim3(HIDM / 64, TOK / 128), 256>>>(h, w1, big, bm1, nullptr,
                                                        TOK, HIDM, CCH);

    // 7) fc2 + residual(y) -> out
    gemm_kernel<3><<<dim3(CCH / 64, TOK / 128), 256>>>(big, w2, out, bm2, y,
                                                       TOK, CCH, HIDM);
}

// round 3
// speedup vs baseline: 1.3117x; 1.3117x over previous
#include <cuda_runtime.h>
#include <cuda_bf16.h>
#include <math.h>
#include <stdint.h>

// Problem constants
#define TOK   100352          // B * H * W = 32*56*56  (= 2048 windows * 49 tokens)
#define CCH   384
#define HID3  1152
#define HIDM  1536
#define NWIN  2048            // B * 64
#define NHEAD 12

// ---------------- scratch (device globals; no allocation allowed) ------------
__device__ float g_h  [(size_t)TOK * CCH];    // windowed LN output / attn out / LN2 out
__device__ float g_big[(size_t)TOK * HIDM];   // qkv (1152 cols used) / mlp hidden (1536)
__device__ float g_y  [(size_t)TOK * CCH];    // residual after attention

// map windowed row t -> flat (b*3136 + h*56 + w) index in the UNSHIFTED image
__device__ __forceinline__ int winrow_to_dst(int t) {
    int n  = t % 49;
    int w_ = t / 49;
    int b  = w_ >> 6;
    int nw = w_ & 63;
    int wh = nw >> 3, ww = nw & 7;
    int r = n / 7, c = n % 7;
    int h = wh * 7 + r + 3; if (h >= 56) h -= 56;   // window reverse + roll(+3)
    int w = ww * 7 + c + 3; if (w >= 56) w -= 56;
    return b * 3136 + h * 56 + w;
}

__device__ __forceinline__ float to_tf32(float x) {
    asm("cvt.rna.tf32.f32 %0, %0;" : "+f"(x));
    return x;
}

// ---------------- LayerNorm (+optional shift/window gather) ------------------
__global__ void ln_kernel(const float* __restrict__ x, const float* __restrict__ g,
                          const float* __restrict__ b, float* __restrict__ out,
                          int windowed)
{
    int t = blockIdx.x;
    size_t src;
    if (windowed) {
        int n  = t % 49;
        int w_ = t / 49;
        int batch = w_ >> 6;
        int nw = w_ & 63;
        int wh = nw >> 3, ww = nw & 7;
        int r = n / 7, c = n % 7;
        int h  = wh * 7 + r + 3; if (h  >= 56) h  -= 56;   // roll(-3)
        int wc = ww * 7 + c + 3; if (wc >= 56) wc -= 56;
        src = ((size_t)batch * 3136 + h * 56 + wc) * CCH;
    } else {
        src = (size_t)t * CCH;
    }
    int tid = threadIdx.x;                 // 128 threads, 3 elems each
    float v0 = x[src + tid];
    float v1 = x[src + tid + 128];
    float v2 = x[src + tid + 256];
    float s  = v0 + v1 + v2;
    float ss = v0 * v0 + v1 * v1 + v2 * v2;
    #pragma unroll
    for (int o = 16; o; o >>= 1) {
        s  += __shfl_xor_sync(0xffffffffu, s,  o);
        ss += __shfl_xor_sync(0xffffffffu, ss, o);
    }
    __shared__ float sh_s[4], sh_q[4];
    int wid = tid >> 5, lane = tid & 31;
    if (lane == 0) { sh_s[wid] = s; sh_q[wid] = ss; }
    __syncthreads();
    float ts = sh_s[0] + sh_s[1] + sh_s[2] + sh_s[3];
    float tq = sh_q[0] + sh_q[1] + sh_q[2] + sh_q[3];
    float mean = ts * (1.0f / 384.0f);
    float var  = tq * (1.0f / 384.0f) - mean * mean;
    float inv  = rsqrtf(var + 1e-5f);
    size_t dst = (size_t)t * CCH;
    out[dst + tid]       = (v0 - mean) * inv * g[tid]       + b[tid];
    out[dst + tid + 128] = (v1 - mean) * inv * g[tid + 128] + b[tid + 128];
    out[dst + tid + 256] = (v2 - mean) * inv * g[tid + 256] + b[tid + 256];
}

// ---------------- tf32 tensor-core GEMM + fused epilogues --------------------
// C[M,N] = A[M,K] @ B[K,N]
// Block 128x128x16, 256 thr = 8 warps (2M x 4N), warp 64x32 = 4x4 m16n8k8.
// MODE 0: C = acc + bias                                (QKV)
// MODE 1: y[dst] = resid[dst] + acc + bias  (window-reverse scatter) (proj)
// MODE 2: C = gelu(acc + bias)                          (MLP fc1)
// MODE 3: C = resid + acc + bias                        (MLP fc2 + residual)
#define AS_STR 20
#define BS_STR 136
template<int MODE>
__global__ void __launch_bounds__(256, 2)
gemm_kernel(const float* __restrict__ A, const float* __restrict__ B,
            float* __restrict__ C, const float* __restrict__ bias,
            const float* __restrict__ resid, int M, int N, int K)
{
    __shared__ __align__(16) float As[128 * AS_STR];   // [m][k] stride 20
    __shared__ __align__(16) float Bs[16 * BS_STR];    // [k][n] stride 136

    int tid  = threadIdx.x;
    int wid  = tid >> 5, lane = tid & 31;
    int wm   = wid & 1, wn = wid >> 1;                 // 2 x 4 warp grid
    int grp  = lane >> 2, tig = lane & 3;              // mma thread mapping
    int m0   = blockIdx.y * 128, n0 = blockIdx.x * 128;

    float acc[4][4][4];
    #pragma unroll
    for (int mi = 0; mi < 4; mi++)
        #pragma unroll
        for (int ni = 0; ni < 4; ni++)
            #pragma unroll
            for (int r = 0; r < 4; r++) acc[mi][ni][r] = 0.0f;

    // gmem->smem mapping (constant across iters)
    int a_row = tid >> 2, a_kc = (tid & 3) << 2;       // + second slot row+64
    int b_row = tid >> 5, b_c4 = (tid & 31) << 2;      // 8 rows x 128 cols / iter

    for (int k0 = 0; k0 < K; k0 += 16) {
        // ---- A tile: 128 rows x 16 k, float4 + tf32 convert ----
        #pragma unroll
        for (int it = 0; it < 2; it++) {
            int row = a_row + it * 64;
            float4 v = *(const float4*)(A + (size_t)(m0 + row) * K + k0 + a_kc);
            v.x = to_tf32(v.x); v.y = to_tf32(v.y);
            v.z = to_tf32(v.z); v.w = to_tf32(v.w);
            *(float4*)&As[row * AS_STR + a_kc] = v;
        }
        // ---- B tile: 16 rows x 128 n ----
        #pragma unroll
        for (int it = 0; it < 2; it++) {
            int row = b_row + it * 8;
            float4 v = *(const float4*)(B + (size_t)(k0 + row) * N + n0 + b_c4);
            v.x = to_tf32(v.x); v.y = to_tf32(v.y);
            v.z = to_tf32(v.z); v.w = to_tf32(v.w);
            *(float4*)&Bs[row * BS_STR + b_c4] = v;
        }
        __syncthreads();

        #pragma unroll
        for (int ks = 0; ks < 16; ks += 8) {
            uint32_t af[4][4], bf[4][2];
            #pragma unroll
            for (int mi = 0; mi < 4; mi++) {
                int r0 = (wm * 64 + mi * 16 + grp) * AS_STR + ks + tig;
                af[mi][0] = __float_as_uint(As[r0]);
                af[mi][1] = __float_as_uint(As[r0 + 8 * AS_STR]);
                af[mi][2] = __float_as_uint(As[r0 + 4]);
                af[mi][3] = __float_as_uint(As[r0 + 8 * AS_STR + 4]);
            }
            #pragma unroll
            for (int ni = 0; ni < 4; ni++) {
                int c0 = (ks + tig) * BS_STR + wn * 32 + ni * 8 + grp;
                bf[ni][0] = __float_as_uint(Bs[c0]);
                bf[ni][1] = __float_as_uint(Bs[c0 + 4 * BS_STR]);
            }
            #pragma unroll
            for (int mi = 0; mi < 4; mi++)
                #pragma unroll
                for (int ni = 0; ni < 4; ni++) {
                    float* d = acc[mi][ni];
                    asm volatile(
                        "mma.sync.aligned.m16n8k8.row.col.f32.tf32.tf32.f32 "
                        "{%0,%1,%2,%3},{%4,%5,%6,%7},{%8,%9},{%0,%1,%2,%3};"
                        : "+f"(d[0]), "+f"(d[1]), "+f"(d[2]), "+f"(d[3])
                        : "r"(af[mi][0]), "r"(af[mi][1]), "r"(af[mi][2]), "r"(af[mi][3]),
                          "r"(bf[ni][0]), "r"(bf[ni][1]));
                }
        }
        __syncthreads();
    }

    // ---- epilogue: two rows (grp, grp+8) per mma tile, float2 col pairs ----
    #pragma unroll
    for (int mi = 0; mi < 4; mi++) {
        int r0 = m0 + wm * 64 + mi * 16 + grp;
        int r1 = r0 + 8;
        int dst0 = 0, dst1 = 0;
        if (MODE == 1) { dst0 = winrow_to_dst(r0); dst1 = winrow_to_dst(r1); }
        #pragma unroll
        for (int ni = 0; ni < 4; ni++) {
            int col = n0 + wn * 32 + ni * 8 + tig * 2;
            float b0 = bias[col], b1 = bias[col + 1];
            float v00 = acc[mi][ni][0] + b0, v01 = acc[mi][ni][1] + b1;
            float v10 = acc[mi][ni][2] + b0, v11 = acc[mi][ni][3] + b1;
            if (MODE == 0) {
                *(float2*)&C[(size_t)r0 * N + col] = make_float2(v00, v01);
                *(float2*)&C[(size_t)r1 * N + col] = make_float2(v10, v11);
            } else if (MODE == 1) {
                size_t o0 = (size_t)dst0 * CCH + col;
                size_t o1 = (size_t)dst1 * CCH + col;
                *(float2*)&C[o0] = make_float2(resid[o0] + v00, resid[o0 + 1] + v01);
                *(float2*)&C[o1] = make_float2(resid[o1] + v10, resid[o1 + 1] + v11);
            } else if (MODE == 2) {
                const float is2 = 0.70710678118654752f;
                v00 = 0.5f * v00 * (1.0f + erff(v00 * is2));
                v01 = 0.5f * v01 * (1.0f + erff(v01 * is2));
                v10 = 0.5f * v10 * (1.0f + erff(v10 * is2));
                v11 = 0.5f * v11 * (1.0f + erff(v11 * is2));
                *(float2*)&C[(size_t)r0 * N + col] = make_float2(v00, v01);
                *(float2*)&C[(size_t)r1 * N + col] = make_float2(v10, v11);
            } else {
                size_t o0 = (size_t)r0 * CCH + col;
                size_t o1 = (size_t)r1 * CCH + col;
                *(float2*)&C[o0] = make_float2(resid[o0] + v00, resid[o0 + 1] + v01);
                *(float2*)&C[o1] = make_float2(resid[o1] + v10, resid[o1 + 1] + v11);
            }
        }
    }
}

// ---------------- windowed attention: one block per (window, head) -----------
__global__ void __launch_bounds__(256)
attn_kernel(const float* __restrict__ qkv, const float* __restrict__ rpb,
            float* __restrict__ out)
{
    int blk  = blockIdx.x;          // 0 .. 24575
    int head = blk % NHEAD;
    int win  = blk / NHEAD;

    __shared__ float Qs[49][32], Ks[49][32], Vs[49][32];
    __shared__ float S[49][52];
    __shared__ int   regio[49];

    int tid = threadIdx.x;
    const float scale = 0.17677669529663687f;   // 32^-0.5
    size_t base = (size_t)win * 49 * HID3 + head * 32;

    for (int idx = tid; idx < 49 * 32; idx += 256) {
        int n = idx >> 5, d = idx & 31;
        size_t rb = base + (size_t)n * HID3 + d;
        Qs[n][d] = qkv[rb] * scale;
        Ks[n][d] = qkv[rb + 384];
        Vs[n][d] = qkv[rb + 768];
    }
    if (tid < 49) {
        int nw = win & 63;
        int wh = nw >> 3, ww = nw & 7;
        int r = tid / 7, c = tid % 7;
        int hh = wh * 7 + r, wg = ww * 7 + c;
        int rh = hh < 49 ? 0 : (hh < 53 ? 1 : 2);
        int rw = wg < 49 ? 0 : (wg < 53 ? 1 : 2);
        regio[tid] = rh * 3 + rw;
    }
    __syncthreads();

    for (int idx = tid; idx < 49 * 49; idx += 256) {
        int i = idx / 49, j = idx % 49;
        float s = 0.0f;
        #pragma unroll
        for (int d = 0; d < 32; d++) s += Qs[i][d] * Ks[j][d];
        int ri = i / 7, ci = i % 7, rj = j / 7, cj = j % 7;
        int rel = (ri - rj + 6) * 13 + (ci - cj + 6);
        s += rpb[rel * NHEAD + head];
        if (regio[i] != regio[j]) s -= 100.0f;
        S[i][j] = s;
    }
    __syncthreads();

    int wid = tid >> 5, lane = tid & 31;
    for (int i = wid; i < 49; i += 8) {
        float v0 = S[i][lane];
        float v1 = (lane + 32 < 49) ? S[i][lane + 32] : -1e30f;
        float m = fmaxf(v0, v1);
        #pragma unroll
        for (int o = 16; o; o >>= 1) m = fmaxf(m, __shfl_xor_sync(0xffffffffu, m, o));
        float e0 = __expf(v0 - m);
        float e1 = (lane + 32 < 49) ? __expf(v1 - m) : 0.0f;
        float sum = e0 + e1;
        #pragma unroll
        for (int o = 16; o; o >>= 1) sum += __shfl_xor_sync(0xffffffffu, sum, o);
        float inv = 1.0f / sum;
        S[i][lane] = e0 * inv;
        if (lane + 32 < 49) S[i][lane + 32] = e1 * inv;
    }
    __syncthreads();

    for (int idx = tid; idx < 49 * 32; idx += 256) {
        int i = idx >> 5, d = idx & 31;
        float o = 0.0f;
        #pragma unroll
        for (int j = 0; j < 49; j++) o += S[i][j] * Vs[j][d];
        out[((size_t)win * 49 + i) * CCH + head * 32 + d] = o;
    }
}

// ---------------------------------- driver -----------------------------------
extern "C" void kernel_launch(void* const* d_in, const int* in_sizes, int n_in,
                              void* d_out, int out_size)
{
    const float* x      = (const float*)d_in[0];
    const float* g1     = (const float*)d_in[1];
    const float* b1     = (const float*)d_in[2];
    const float* w_qkv  = (const float*)d_in[3];
    const float* b_qkv  = (const float*)d_in[4];
    const float* w_proj = (const float*)d_in[5];
    const float* b_proj = (const float*)d_in[6];
    const float* rpb    = (const float*)d_in[7];
    const float* g2     = (const float*)d_in[8];
    const float* b2     = (const float*)d_in[9];
    const float* w1     = (const float*)d_in[10];
    const float* bm1    = (const float*)d_in[11];
    const float* w2     = (const float*)d_in[12];
    const float* bm2    = (const float*)d_in[13];
    float* out = (float*)d_out;

    float *h, *big, *y;
    cudaGetSymbolAddress((void**)&h,   g_h);
    cudaGetSymbolAddress((void**)&big, g_big);
    cudaGetSymbolAddress((void**)&y,   g_y);

    // 1) LN1 + roll(-3,-3) + window partition -> h [100352, 384]
    ln_kernel<<<TOK, 128>>>(x, g1, b1, h, 1);

    // 2) QKV: h @ w_qkv + b_qkv -> big [100352, 1152]
    gemm_kernel<0><<<dim3(HID3 / 128, TOK / 128), 256>>>(h, w_qkv, big, b_qkv, nullptr,
                                                         TOK, HID3, CCH);

    // 3) attention per (window, head) -> h [100352, 384]
    attn_kernel<<<NWIN * NHEAD, 256>>>(big, rpb, h);

    // 4) proj + window reverse + roll(+3,+3) + residual(x) -> y [100352, 384]
    gemm_kernel<1><<<dim3(CCH / 128, TOK / 128), 256>>>(h, w_proj, y, b_proj, x,
                                                        TOK, CCH, CCH);

    // 5) LN2 -> h
    ln_kernel<<<TOK, 128>>>(y, g2, b2, h, 0);

    // 6) fc1 + exact GELU -> big [100352, 1536]
    gemm_kernel<2><<<dim3(HIDM / 128, TOK / 128), 256>>>(h, w1, big, bm1, nullptr,
                                                         TOK, HIDM, CCH);

    // 7) fc2 + residual(y) -> out
    gemm_kernel<3><<<dim3(CCH / 128, TOK / 128), 256>>>(big, w2, out, bm2, y,
                                                        TOK, CCH, HIDM);
}

// round 4
// speedup vs baseline: 2.2505x; 1.7158x over previous
#include <cuda_runtime.h>
#include <cuda_bf16.h>
#include <math.h>
#include <stdint.h>

// Problem constants
#define TOK   100352          // B * H * W = 32*56*56  (= 2048 windows * 49 tokens)
#define CCH   384
#define HID3  1152
#define HIDM  1536
#define NWIN  2048            // B * 64
#define NHEAD 12

// ---------------- scratch (device globals; no allocation allowed) ------------
__device__ float g_h  [(size_t)TOK * CCH];
__device__ float g_big[(size_t)TOK * HIDM];
__device__ float g_y  [(size_t)TOK * CCH];

// map windowed row t -> flat (b*3136 + h*56 + w) index in the UNSHIFTED image
__device__ __forceinline__ int winrow_to_dst(int t) {
    int n  = t % 49;
    int w_ = t / 49;
    int b  = w_ >> 6;
    int nw = w_ & 63;
    int wh = nw >> 3, ww = nw & 7;
    int r = n / 7, c = n % 7;
    int h = wh * 7 + r + 3; if (h >= 56) h -= 56;
    int w = ww * 7 + c + 3; if (w >= 56) w -= 56;
    return b * 3136 + h * 56 + w;
}

__device__ __forceinline__ void cp16(uint32_t s, const float* g) {
    asm volatile("cp.async.ca.shared.global [%0], [%1], 16;" :: "r"(s), "l"(g));
}

// ---------------- LayerNorm (+optional shift/window gather) ------------------
__global__ void ln_kernel(const float* __restrict__ x, const float* __restrict__ g,
                          const float* __restrict__ b, float* __restrict__ out,
                          int windowed)
{
    int t = blockIdx.x;
    size_t src;
    if (windowed) {
        int n  = t % 49;
        int w_ = t / 49;
        int batch = w_ >> 6;
        int nw = w_ & 63;
        int wh = nw >> 3, ww = nw & 7;
        int r = n / 7, c = n % 7;
        int h  = wh * 7 + r + 3; if (h  >= 56) h  -= 56;
        int wc = ww * 7 + c + 3; if (wc >= 56) wc -= 56;
        src = ((size_t)batch * 3136 + h * 56 + wc) * CCH;
    } else {
        src = (size_t)t * CCH;
    }
    int tid = threadIdx.x;
    float v0 = x[src + tid];
    float v1 = x[src + tid + 128];
    float v2 = x[src + tid + 256];
    float s  = v0 + v1 + v2;
    float ss = v0 * v0 + v1 * v1 + v2 * v2;
    #pragma unroll
    for (int o = 16; o; o >>= 1) {
        s  += __shfl_xor_sync(0xffffffffu, s,  o);
        ss += __shfl_xor_sync(0xffffffffu, ss, o);
    }
    __shared__ float sh_s[4], sh_q[4];
    int wid = tid >> 5, lane = tid & 31;
    if (lane == 0) { sh_s[wid] = s; sh_q[wid] = ss; }
    __syncthreads();
    float ts = sh_s[0] + sh_s[1] + sh_s[2] + sh_s[3];
    float tq = sh_q[0] + sh_q[1] + sh_q[2] + sh_q[3];
    float mean = ts * (1.0f / 384.0f);
    float var  = tq * (1.0f / 384.0f) - mean * mean;
    float inv  = rsqrtf(var + 1e-5f);
    size_t dst = (size_t)t * CCH;
    out[dst + tid]       = (v0 - mean) * inv * g[tid]       + b[tid];
    out[dst + tid + 128] = (v1 - mean) * inv * g[tid + 128] + b[tid + 128];
    out[dst + tid + 256] = (v2 - mean) * inv * g[tid + 256] + b[tid + 256];
}

// ---------------- tf32 tensor-core GEMM, cp.async 2-stage, ldmatrix A --------
// C[M,N] = A[M,K] @ B[K,N]
// Block 128x128x16, 256 thr = 8 warps (2M x 4N), warp 64x32 = 4x4 m16n8k8.
#define AS_STR 20
#define BS_STR 136
#define AS_TSZ (128 * AS_STR)
#define BS_TSZ (16 * BS_STR)
template<int MODE>
__global__ void __launch_bounds__(256, 2)
gemm_kernel(const float* __restrict__ A, const float* __restrict__ B,
            float* __restrict__ C, const float* __restrict__ bias,
            const float* __restrict__ resid, int M, int N, int K)
{
    __shared__ __align__(16) float As[2][AS_TSZ];
    __shared__ __align__(16) float Bs[2][BS_TSZ];

    int tid  = threadIdx.x;
    int wid  = tid >> 5, lane = tid & 31;
    int wm   = wid & 1, wn = wid >> 1;
    int grp  = lane >> 2, tig = lane & 3;
    int m0   = blockIdx.y * 128, n0 = blockIdx.x * 128;

    float acc[4][4][4];
    #pragma unroll
    for (int mi = 0; mi < 4; mi++)
        #pragma unroll
        for (int ni = 0; ni < 4; ni++)
            #pragma unroll
            for (int r = 0; r < 4; r++) acc[mi][ni][r] = 0.0f;

    // fill mappings
    int a_row = tid >> 2, a_kc = (tid & 3) << 2;     // + row+64 second chunk
    int b_row = tid >> 5, b_nc = (tid & 31) << 2;    // + row+8 second chunk

    uint32_t sA0 = (uint32_t)__cvta_generic_to_shared(&As[0][0]);
    uint32_t sB0 = (uint32_t)__cvta_generic_to_shared(&Bs[0][0]);

    const float* gA = A + (size_t)(m0 + a_row) * K + a_kc;   // advance by k0
    const float* gB = B + (size_t)b_row * N + n0 + b_nc;

    // ldmatrix per-lane base for A fragments (within a stage)
    uint32_t a_lm_off = (uint32_t)(((wm * 64 + (lane & 15)) * AS_STR + ((lane >> 4) << 2)) * 4);

    int T = K >> 4;   // k-tiles

    // prologue: stage 0
    {
        cp16(sA0 + (uint32_t)((a_row * AS_STR + a_kc) * 4),        gA);
        cp16(sA0 + (uint32_t)(((a_row + 64) * AS_STR + a_kc) * 4), gA + (size_t)64 * K);
        cp16(sB0 + (uint32_t)((b_row * BS_STR + b_nc) * 4),        gB);
        cp16(sB0 + (uint32_t)(((b_row + 8) * BS_STR + b_nc) * 4),  gB + (size_t)8 * N);
        asm volatile("cp.async.commit_group;");
    }

    for (int t = 0; t < T; t++) {
        int cur = t & 1;
        if (t + 1 < T) {
            int nxt = cur ^ 1;
            const float* gA2 = gA + (t + 1) * 16;
            const float* gB2 = gB + (size_t)(t + 1) * 16 * N;
            uint32_t sA = sA0 + (uint32_t)(nxt * AS_TSZ * 4);
            uint32_t sB = sB0 + (uint32_t)(nxt * BS_TSZ * 4);
            cp16(sA + (uint32_t)((a_row * AS_STR + a_kc) * 4),        gA2);
            cp16(sA + (uint32_t)(((a_row + 64) * AS_STR + a_kc) * 4), gA2 + (size_t)64 * K);
            cp16(sB + (uint32_t)((b_row * BS_STR + b_nc) * 4),        gB2);
            cp16(sB + (uint32_t)(((b_row + 8) * BS_STR + b_nc) * 4),  gB2 + (size_t)8 * N);
            asm volatile("cp.async.commit_group;");
            asm volatile("cp.async.wait_group 1;");
        } else {
            asm volatile("cp.async.wait_group 0;");
        }
        __syncthreads();

        uint32_t aStage = sA0 + (uint32_t)(cur * AS_TSZ * 4) + a_lm_off;
        const float* bsm = &Bs[cur][0];

        #pragma unroll
        for (int ks = 0; ks < 16; ks += 8) {
            uint32_t af[4][4], bf[4][2];
            #pragma unroll
            for (int mi = 0; mi < 4; mi++) {
                uint32_t ad = aStage + (uint32_t)((mi * 16 * AS_STR + ks) * 4);
                asm volatile("ldmatrix.sync.aligned.m8n8.x4.b16 {%0,%1,%2,%3}, [%4];"
                             : "=r"(af[mi][0]), "=r"(af[mi][1]),
                               "=r"(af[mi][2]), "=r"(af[mi][3]) : "r"(ad));
            }
            #pragma unroll
            for (int ni = 0; ni < 4; ni++) {
                int c0 = (ks + tig) * BS_STR + wn * 32 + ni * 8 + grp;
                bf[ni][0] = __float_as_uint(bsm[c0]);
                bf[ni][1] = __float_as_uint(bsm[c0 + 4 * BS_STR]);
            }
            #pragma unroll
            for (int mi = 0; mi < 4; mi++)
                #pragma unroll
                for (int ni = 0; ni < 4; ni++) {
                    float* d = acc[mi][ni];
                    asm volatile(
                        "mma.sync.aligned.m16n8k8.row.col.f32.tf32.tf32.f32 "
                        "{%0,%1,%2,%3},{%4,%5,%6,%7},{%8,%9},{%0,%1,%2,%3};"
                        : "+f"(d[0]), "+f"(d[1]), "+f"(d[2]), "+f"(d[3])
                        : "r"(af[mi][0]), "r"(af[mi][1]), "r"(af[mi][2]), "r"(af[mi][3]),
                          "r"(bf[ni][0]), "r"(bf[ni][1]));
                }
        }
        __syncthreads();
    }

    // ---- epilogue ----
    #pragma unroll
    for (int mi = 0; mi < 4; mi++) {
        int r0 = m0 + wm * 64 + mi * 16 + grp;
        int r1 = r0 + 8;
        int dst0 = 0, dst1 = 0;
        if (MODE == 1) { dst0 = winrow_to_dst(r0); dst1 = winrow_to_dst(r1); }
        #pragma unroll
        for (int ni = 0; ni < 4; ni++) {
            int col = n0 + wn * 32 + ni * 8 + tig * 2;
            float b0 = bias[col], b1 = bias[col + 1];
            float v00 = acc[mi][ni][0] + b0, v01 = acc[mi][ni][1] + b1;
            float v10 = acc[mi][ni][2] + b0, v11 = acc[mi][ni][3] + b1;
            if (MODE == 0) {
                *(float2*)&C[(size_t)r0 * N + col] = make_float2(v00, v01);
                *(float2*)&C[(size_t)r1 * N + col] = make_float2(v10, v11);
            } else if (MODE == 1) {
                size_t o0 = (size_t)dst0 * CCH + col;
                size_t o1 = (size_t)dst1 * CCH + col;
                *(float2*)&C[o0] = make_float2(resid[o0] + v00, resid[o0 + 1] + v01);
                *(float2*)&C[o1] = make_float2(resid[o1] + v10, resid[o1 + 1] + v11);
            } else if (MODE == 2) {
                const float is2 = 0.70710678118654752f;
                v00 = 0.5f * v00 * (1.0f + erff(v00 * is2));
                v01 = 0.5f * v01 * (1.0f + erff(v01 * is2));
                v10 = 0.5f * v10 * (1.0f + erff(v10 * is2));
                v11 = 0.5f * v11 * (1.0f + erff(v11 * is2));
                *(float2*)&C[(size_t)r0 * N + col] = make_float2(v00, v01);
                *(float2*)&C[(size_t)r1 * N + col] = make_float2(v10, v11);
            } else {
                size_t o0 = (size_t)r0 * CCH + col;
                size_t o1 = (size_t)r1 * CCH + col;
                *(float2*)&C[o0] = make_float2(resid[o0] + v00, resid[o0 + 1] + v01);
                *(float2*)&C[o1] = make_float2(resid[o1] + v10, resid[o1 + 1] + v11);
            }
        }
    }
}

// ---------------- windowed attention: one block per (window, head) -----------
__global__ void __launch_bounds__(256)
attn_kernel(const float* __restrict__ qkv, const float* __restrict__ rpb,
            float* __restrict__ out)
{
    int blk  = blockIdx.x;
    int head = blk % NHEAD;
    int win  = blk / NHEAD;

    __shared__ float Qs[49][32], Ks[49][32], Vs[49][32];
    __shared__ float S[49][52];
    __shared__ int   regio[49];

    int tid = threadIdx.x;
    const float scale = 0.17677669529663687f;
    size_t base = (size_t)win * 49 * HID3 + head * 32;

    for (int idx = tid; idx < 49 * 32; idx += 256) {
        int n = idx >> 5, d = idx & 31;
        size_t rb = base + (size_t)n * HID3 + d;
        Qs[n][d] = qkv[rb] * scale;
        Ks[n][d] = qkv[rb + 384];
        Vs[n][d] = qkv[rb + 768];
    }
    if (tid < 49) {
        int nw = win & 63;
        int wh = nw >> 3, ww = nw & 7;
        int r = tid / 7, c = tid % 7;
        int hh = wh * 7 + r, wg = ww * 7 + c;
        int rh = hh < 49 ? 0 : (hh < 53 ? 1 : 2);
        int rw = wg < 49 ? 0 : (wg < 53 ? 1 : 2);
        regio[tid] = rh * 3 + rw;
    }
    __syncthreads();

    for (int idx = tid; idx < 49 * 49; idx += 256) {
        int i = idx / 49, j = idx % 49;
        float s = 0.0f;
        #pragma unroll
        for (int d = 0; d < 32; d++) s += Qs[i][d] * Ks[j][d];
        int ri = i / 7, ci = i % 7, rj = j / 7, cj = j % 7;
        int rel = (ri - rj + 6) * 13 + (ci - cj + 6);
        s += rpb[rel * NHEAD + head];
        if (regio[i] != regio[j]) s -= 100.0f;
        S[i][j] = s;
    }
    __syncthreads();

    int wid = tid >> 5, lane = tid & 31;
    for (int i = wid; i < 49; i += 8) {
        float v0 = S[i][lane];
        float v1 = (lane + 32 < 49) ? S[i][lane + 32] : -1e30f;
        float m = fmaxf(v0, v1);
        #pragma unroll
        for (int o = 16; o; o >>= 1) m = fmaxf(m, __shfl_xor_sync(0xffffffffu, m, o));
        float e0 = __expf(v0 - m);
        float e1 = (lane + 32 < 49) ? __expf(v1 - m) : 0.0f;
        float sum = e0 + e1;
        #pragma unroll
        for (int o = 16; o; o >>= 1) sum += __shfl_xor_sync(0xffffffffu, sum, o);
        float inv = 1.0f / sum;
        S[i][lane] = e0 * inv;
        if (lane + 32 < 49) S[i][lane + 32] = e1 * inv;
    }
    __syncthreads();

    for (int idx = tid; idx < 49 * 32; idx += 256) {
        int i = idx >> 5, d = idx & 31;
        float o = 0.0f;
        #pragma unroll
        for (int j = 0; j < 49; j++) o += S[i][j] * Vs[j][d];
        out[((size_t)win * 49 + i) * CCH + head * 32 + d] = o;
    }
}

// ---------------------------------- driver -----------------------------------
extern "C" void kernel_launch(void* const* d_in, const int* in_sizes, int n_in,
                              void* d_out, int out_size)
{
    const float* x      = (const float*)d_in[0];
    const float* g1     = (const float*)d_in[1];
    const float* b1     = (const float*)d_in[2];
    const float* w_qkv  = (const float*)d_in[3];
    const float* b_qkv  = (const float*)d_in[4];
    const float* w_proj = (const float*)d_in[5];
    const float* b_proj = (const float*)d_in[6];
    const float* rpb    = (const float*)d_in[7];
    const float* g2     = (const float*)d_in[8];
    const float* b2     = (const float*)d_in[9];
    const float* w1     = (const float*)d_in[10];
    const float* bm1    = (const float*)d_in[11];
    const float* w2     = (const float*)d_in[12];
    const float* bm2    = (const float*)d_in[13];
    float* out = (float*)d_out;

    float *h, *big, *y;
    cudaGetSymbolAddress((void**)&h,   g_h);
    cudaGetSymbolAddress((void**)&big, g_big);
    cudaGetSymbolAddress((void**)&y,   g_y);

    // 1) LN1 + roll(-3,-3) + window partition -> h [100352, 384]
    ln_kernel<<<TOK, 128>>>(x, g1, b1, h, 1);

    // 2) QKV: h @ w_qkv + b_qkv -> big [100352, 1152]
    gemm_kernel<0><<<dim3(HID3 / 128, TOK / 128), 256>>>(h, w_qkv, big, b_qkv, nullptr,
                                                         TOK, HID3, CCH);

    // 3) attention per (window, head) -> h [100352, 384]
    attn_kernel<<<NWIN * NHEAD, 256>>>(big, rpb, h);

    // 4) proj + window reverse + roll(+3,+3) + residual(x) -> y [100352, 384]
    gemm_kernel<1><<<dim3(CCH / 128, TOK / 128), 256>>>(h, w_proj, y, b_proj, x,
                                                        TOK, CCH, CCH);

    // 5) LN2 -> h
    ln_kernel<<<TOK, 128>>>(y, g2, b2, h, 0);

    // 6) fc1 + exact GELU -> big [100352, 1536]
    gemm_kernel<2><<<dim3(HIDM / 128, TOK / 128), 256>>>(h, w1, big, bm1, nullptr,
                                                         TOK, HIDM, CCH);

    // 7) fc2 + residual(y) -> out
    gemm_kernel<3><<<dim3(CCH / 128, TOK / 128), 256>>>(big, w2, out, bm2, y,
                                                        TOK, CCH, HIDM);
}